// round 15
// baseline (speedup 1.0000x reference)
#include <cuda_runtime.h>
#include <cuda_bf16.h>

#define SPL_EPS 1e-12f
#define NKNOTS 30
#define NSEG   29

// PCHIP spline, uniform knots. Per segment: y = c0 + t*(c1 + t*(c2 + t*c3)).
// - 29-segment float4 LUT replicated per-lane in smem -> conflict-free LDS.128
//   for any index pattern (lane l's slot starts at bank 4l mod 32; each 8-lane
//   phase of an LDS.128 covers all 32 banks exactly once).
// - __launch_bounds__(256,8): 32 regs, 8 CTAs/SM, 148*8 grid = exactly 1 wave.
// - Simple grid-stride float4 loop (bench-best shape).
__global__ void __launch_bounds__(256, 8)
spline_eval_kernel(const float* __restrict__ x,
                   const float* __restrict__ knots,
                   const float* __restrict__ coeffs,
                   float* __restrict__ out,
                   int n)
{
    __shared__ float  s_k[NKNOTS];
    __shared__ float  s_y[NKNOTS];
    __shared__ float  s_h[NSEG];
    __shared__ float  s_delta[NSEG];
    __shared__ float  s_d[NKNOTS];
    __shared__ float4 s_c[NSEG];
    __shared__ float4 s_crep[NSEG][32];   // replicated, conflict-free
    __shared__ float  s_scal[3];          // k0, kN, invH

    const int tid  = threadIdx.x;
    const int lane = tid & 31;

    // ---- tiny PCHIP prep, redundantly per block ----
    if (tid < NKNOTS) {
        s_k[tid] = knots[tid];
        s_y[tid] = coeffs[tid];
    }
    __syncthreads();
    if (tid < NSEG) {
        float h = s_k[tid + 1] - s_k[tid];
        s_h[tid]     = h;
        s_delta[tid] = (s_y[tid + 1] - s_y[tid]) / (h + SPL_EPS);
    }
    __syncthreads();
    if (tid < NKNOTS) {
        float d;
        if (tid == 0) {
            float h0 = s_h[0], h1 = s_h[1];
            float de0 = s_delta[0], de1 = s_delta[1];
            d = ((2.0f * h0 + h1) * de0 - h0 * de1) / (h0 + h1 + SPL_EPS);
            if (d * de0 <= 0.0f)                 d = 0.0f;
            else if (fabsf(d) > 3.0f * fabsf(de0)) d = 3.0f * de0;
        } else if (tid == NKNOTS - 1) {
            float hl = s_h[NSEG - 1], hp = s_h[NSEG - 2];
            float del = s_delta[NSEG - 1], dep = s_delta[NSEG - 2];
            d = ((2.0f * hl + hp) * del - hl * dep) / (hl + hp + SPL_EPS);
            if (d * del <= 0.0f)                 d = 0.0f;
            else if (fabsf(d) > 3.0f * fabsf(del)) d = 3.0f * del;
        } else {
            float hkm1 = s_h[tid - 1], hk = s_h[tid];
            float dm = s_delta[tid - 1], dp = s_delta[tid];
            float w1 = 2.0f * hk + hkm1;
            float w2 = hk + 2.0f * hkm1;
            float dint = (w1 + w2) / (w1 / (dm + SPL_EPS) + w2 / (dp + SPL_EPS));
            d = (dm * dp > 0.0f) ? dint : 0.0f;
        }
        s_d[tid] = d;
    }
    __syncthreads();
    if (tid < NSEG) {
        float h      = s_h[tid];
        float safe_h = (fabsf(h) < SPL_EPS) ? 1.0f : h;
        float yk  = s_y[tid], yk1 = s_y[tid + 1];
        float hd0 = safe_h * s_d[tid];
        float hd1 = safe_h * s_d[tid + 1];
        float4 c;
        c.x = yk;
        c.y = hd0;
        c.z = -3.0f * yk - 2.0f * hd0 + 3.0f * yk1 - hd1;
        c.w =  2.0f * yk +        hd0 - 2.0f * yk1 + hd1;
        s_c[tid] = c;
    }
    if (tid == 0) {
        float k0 = s_k[0];
        float kN = s_k[NKNOTS - 1];
        s_scal[0] = k0;
        s_scal[1] = kN;
        // knots are linspace -> uniform segment width.
        s_scal[2] = (float)(NKNOTS - 1) / (kN - k0);
    }
    __syncthreads();

    // Replicate the coefficient table across the 32 lane slots.
    for (int i = tid; i < NSEG * 32; i += blockDim.x) {
        s_crep[i >> 5][i & 31] = s_c[i >> 5];
    }
    __syncthreads();

    const float k0   = s_scal[0];
    const float kN   = s_scal[1];
    const float invH = s_scal[2];
    const float4* __restrict__ lut = &s_crep[0][lane];  // stride 32 float4s

    auto eval1 = [&](float xv) -> float {
        float xc = fminf(fmaxf(xv, k0), kN);
        float s  = (xc - k0) * invH;
        // xc >= k0 -> s >= 0, so only the upper clamp is needed.
        int idx  = (int)s;
        idx = idx > NSEG - 1 ? NSEG - 1 : idx;
        float t  = s - (float)idx;
        float4 c = lut[idx << 5];   // conflict-free LDS.128
        return fmaf(t, fmaf(t, fmaf(t, c.w, c.z), c.y), c.x);
    };
    auto eval4 = [&](float4 xv) -> float4 {
        float4 yv;
        yv.x = eval1(xv.x);
        yv.y = eval1(xv.y);
        yv.z = eval1(xv.z);
        yv.w = eval1(xv.w);
        return yv;
    };

    // ---- streaming evaluation, float4 vectorized grid-stride ----
    const int n4  = n >> 2;
    const int gsz = gridDim.x * blockDim.x;
    const float4* __restrict__ x4 = (const float4*)x;
    float4* __restrict__ o4 = (float4*)out;

    for (int i = blockIdx.x * blockDim.x + tid; i < n4; i += gsz) {
        o4[i] = eval4(x4[i]);
    }
    // scalar tail (n not divisible by 4)
    for (int j = (n4 << 2) + blockIdx.x * blockDim.x + tid; j < n; j += gsz) {
        out[j] = eval1(x[j]);
    }
}

extern "C" void kernel_launch(void* const* d_in, const int* in_sizes, int n_in,
                              void* d_out, int out_size)
{
    const float* x      = (const float*)d_in[0];
    const float* knots  = (const float*)d_in[1];
    const float* coeffs = (const float*)d_in[2];
    float* out          = (float*)d_out;
    const int n         = in_sizes[0];

    const int threads = 256;
    int blocks = 148 * 8;   // exactly one wave at 8 CTAs/SM
    int work4  = (n >> 2);
    if (work4 > 0) {
        int need = (work4 + threads - 1) / threads;
        if (blocks > need) blocks = need;
    }
    if (blocks < 1) blocks = 1;

    spline_eval_kernel<<<blocks, threads>>>(x, knots, coeffs, out, n);
}

// round 16
// speedup vs baseline: 1.0818x; 1.0818x over previous
#include <cuda_runtime.h>
#include <cuda_bf16.h>

#define SPL_EPS 1e-12f
#define NKNOTS 30
#define NSEG   29

// PCHIP spline, uniform knots. Per segment: y = c0 + t*(c1 + t*(c2 + t*c3)).
// - 29-segment float4 LUT replicated per-lane in smem -> conflict-free LDS.128
//   for any index pattern (lane l's slot starts at bank 4l mod 32; each 8-lane
//   phase of an LDS.128 covers all 32 banks exactly once).
// - __launch_bounds__(256,8): 32 regs, 8 CTAs/SM, 148*8 grid = exactly 1 wave.
// - 2x front-batched LDG.128 per loop trip (MLP): ncu-proven best shape.
__global__ void __launch_bounds__(256, 8)
spline_eval_kernel(const float* __restrict__ x,
                   const float* __restrict__ knots,
                   const float* __restrict__ coeffs,
                   float* __restrict__ out,
                   int n)
{
    __shared__ float  s_k[NKNOTS];
    __shared__ float  s_y[NKNOTS];
    __shared__ float  s_h[NSEG];
    __shared__ float  s_delta[NSEG];
    __shared__ float  s_d[NKNOTS];
    __shared__ float4 s_c[NSEG];
    __shared__ float4 s_crep[NSEG][32];   // replicated, conflict-free
    __shared__ float  s_scal[3];          // k0, kN, invH

    const int tid  = threadIdx.x;
    const int lane = tid & 31;

    // ---- tiny PCHIP prep, redundantly per block ----
    if (tid < NKNOTS) {
        s_k[tid] = knots[tid];
        s_y[tid] = coeffs[tid];
    }
    __syncthreads();
    if (tid < NSEG) {
        float h = s_k[tid + 1] - s_k[tid];
        s_h[tid]     = h;
        s_delta[tid] = (s_y[tid + 1] - s_y[tid]) / (h + SPL_EPS);
    }
    __syncthreads();
    if (tid < NKNOTS) {
        float d;
        if (tid == 0) {
            float h0 = s_h[0], h1 = s_h[1];
            float de0 = s_delta[0], de1 = s_delta[1];
            d = ((2.0f * h0 + h1) * de0 - h0 * de1) / (h0 + h1 + SPL_EPS);
            if (d * de0 <= 0.0f)                 d = 0.0f;
            else if (fabsf(d) > 3.0f * fabsf(de0)) d = 3.0f * de0;
        } else if (tid == NKNOTS - 1) {
            float hl = s_h[NSEG - 1], hp = s_h[NSEG - 2];
            float del = s_delta[NSEG - 1], dep = s_delta[NSEG - 2];
            d = ((2.0f * hl + hp) * del - hl * dep) / (hl + hp + SPL_EPS);
            if (d * del <= 0.0f)                 d = 0.0f;
            else if (fabsf(d) > 3.0f * fabsf(del)) d = 3.0f * del;
        } else {
            float hkm1 = s_h[tid - 1], hk = s_h[tid];
            float dm = s_delta[tid - 1], dp = s_delta[tid];
            float w1 = 2.0f * hk + hkm1;
            float w2 = hk + 2.0f * hkm1;
            float dint = (w1 + w2) / (w1 / (dm + SPL_EPS) + w2 / (dp + SPL_EPS));
            d = (dm * dp > 0.0f) ? dint : 0.0f;
        }
        s_d[tid] = d;
    }
    __syncthreads();
    if (tid < NSEG) {
        float h      = s_h[tid];
        float safe_h = (fabsf(h) < SPL_EPS) ? 1.0f : h;
        float yk  = s_y[tid], yk1 = s_y[tid + 1];
        float hd0 = safe_h * s_d[tid];
        float hd1 = safe_h * s_d[tid + 1];
        float4 c;
        c.x = yk;
        c.y = hd0;
        c.z = -3.0f * yk - 2.0f * hd0 + 3.0f * yk1 - hd1;
        c.w =  2.0f * yk +        hd0 - 2.0f * yk1 + hd1;
        s_c[tid] = c;
    }
    if (tid == 0) {
        float k0 = s_k[0];
        float kN = s_k[NKNOTS - 1];
        s_scal[0] = k0;
        s_scal[1] = kN;
        // knots are linspace -> uniform segment width.
        s_scal[2] = (float)(NKNOTS - 1) / (kN - k0);
    }
    __syncthreads();

    // Replicate the coefficient table across the 32 lane slots.
    for (int i = tid; i < NSEG * 32; i += blockDim.x) {
        s_crep[i >> 5][i & 31] = s_c[i >> 5];
    }
    __syncthreads();

    const float k0   = s_scal[0];
    const float kN   = s_scal[1];
    const float invH = s_scal[2];
    const float b0   = -k0 * invH;          // s = xc*invH + b0 (single FMA)
    const float4* __restrict__ lut = &s_crep[0][lane];  // stride 32 float4s

    auto eval1 = [&](float xv) -> float {
        float xc = fminf(fmaxf(xv, k0), kN);
        float s  = fmaf(xc, invH, b0);
        // xc >= k0 -> s >= 0 (up to rounding clamped below), only upper clamp needed.
        int idx  = (int)s;
        idx = idx > NSEG - 1 ? NSEG - 1 : idx;
        float t  = s - (float)idx;
        float4 c = lut[idx << 5];   // conflict-free LDS.128
        return fmaf(t, fmaf(t, fmaf(t, c.w, c.z), c.y), c.x);
    };
    auto eval4 = [&](float4 xv) -> float4 {
        float4 yv;
        yv.x = eval1(xv.x);
        yv.y = eval1(xv.y);
        yv.z = eval1(xv.z);
        yv.w = eval1(xv.w);
        return yv;
    };

    // ---- streaming evaluation, float4 grid-stride, 2x front-batched loads ----
    const int n4  = n >> 2;
    const int gsz = gridDim.x * blockDim.x;
    const float4* __restrict__ x4 = (const float4*)x;
    float4* __restrict__ o4 = (float4*)out;

    int i = blockIdx.x * blockDim.x + tid;
    for (; i + gsz < n4; i += 2 * gsz) {
        float4 a = x4[i];
        float4 b = x4[i + gsz];
        o4[i]       = eval4(a);
        o4[i + gsz] = eval4(b);
    }
    for (; i < n4; i += gsz) {
        o4[i] = eval4(x4[i]);
    }
    // scalar tail (n not divisible by 4)
    for (int j = (n4 << 2) + blockIdx.x * blockDim.x + tid; j < n; j += gsz) {
        out[j] = eval1(x[j]);
    }
}

extern "C" void kernel_launch(void* const* d_in, const int* in_sizes, int n_in,
                              void* d_out, int out_size)
{
    const float* x      = (const float*)d_in[0];
    const float* knots  = (const float*)d_in[1];
    const float* coeffs = (const float*)d_in[2];
    float* out          = (float*)d_out;
    const int n         = in_sizes[0];

    const int threads = 256;
    int blocks = 148 * 8;   // exactly one wave at 8 CTAs/SM
    int work4  = (n >> 2);
    if (work4 > 0) {
        int need = (work4 + threads - 1) / threads;
        if (blocks > need) blocks = need;
    }
    if (blocks < 1) blocks = 1;

    spline_eval_kernel<<<blocks, threads>>>(x, knots, coeffs, out, n);
}